// round 3
// baseline (speedup 1.0000x reference)
#include <cuda_runtime.h>
#include <cuda_bf16.h>

// BoundaryLoss: loss = sum_{b,c,d,h,w} Gx(q)^2 + 2*Gy(q)^2 (normalized),
// q = softmax(pred, axis=C) - onehot(target); 2-D sobel per depth slice.
// pred (2,4,96,160,160) f32, target (2,96,160,160) i32.

#define BB 2
#define CC 4
#define DD 96
#define HH 160
#define WW 160

#define TH 16                       // output rows per block
#define HALO (TH + 2)               // 18
#define RTILES (HH / TH)            // 10
#define NBLK (BB * DD * RTILES)     // 1920
#define NTHREADS 320
#define PITCH 168                   // [4 guard][160 data][4 guard]

#define CHSTR (DD * HH * WW)
#define CHSTR4 (CHSTR / 4)

__device__ float g_partial[NBLK];
__device__ int   g_count = 0;

// ---- packed f32x2 helpers (sm_100+) ----
typedef unsigned long long u64t;
__device__ __forceinline__ u64t pk2(float lo, float hi) {
    u64t r; asm("mov.b64 %0, {%1, %2};" : "=l"(r) : "f"(lo), "f"(hi)); return r;
}
__device__ __forceinline__ void upk2(float& lo, float& hi, u64t v) {
    asm("mov.b64 {%0, %1}, %2;" : "=f"(lo), "=f"(hi) : "l"(v));
}
__device__ __forceinline__ u64t add2(u64t a, u64t b) {
    u64t r; asm("add.rn.f32x2 %0, %1, %2;" : "=l"(r) : "l"(a), "l"(b)); return r;
}
__device__ __forceinline__ u64t sub2(u64t a, u64t b) {
    u64t r; asm("sub.rn.f32x2 %0, %1, %2;" : "=l"(r) : "l"(a), "l"(b)); return r;
}
__device__ __forceinline__ u64t fma2v(u64t a, u64t b, u64t c) {
    u64t r; asm("fma.rn.f32x2 %0, %1, %2, %3;" : "=l"(r) : "l"(a), "l"(b), "l"(c)); return r;
}

__global__ __launch_bounds__(NTHREADS, 4)
void bl_main_kernel(const float* __restrict__ pred,
                    const int*   __restrict__ target,
                    float*       __restrict__ out)
{
    __shared__ float q[CC][HALO][PITCH];       // 48384 B
    __shared__ float warpsum[NTHREADS / 32];
    __shared__ double dwarpsum[NTHREADS / 32];
    __shared__ bool  is_last;

    const int blk   = blockIdx.x;
    const int rt    = blk % RTILES;
    const int slice = blk / RTILES;
    const int b     = slice / DD;
    const int d     = slice - b * DD;
    const int h0    = rt * TH;

    const float* pred_bd = pred + (size_t)(b * CC * DD + d) * (HH * WW);
    const int*   tgt_bd  = target + (size_t)(b * DD + d) * (HH * WW);

    const int tid = threadIdx.x;

    // ---- guard columns: zero [0..3] and [164..167] for every (c,row) ----
    if (tid < CC * HALO * 2) {
        const int c    = tid / (HALO * 2);
        const int rem  = tid - c * (HALO * 2);
        const int row  = rem >> 1;
        const int side = rem & 1;
        *(float4*)&q[c][row][side ? (4 + WW) : 0] = make_float4(0.f, 0.f, 0.f, 0.f);
    }

    // ---- Phase 1: q = softmax - onehot (no max-sub; inputs are O(1)) ----
    for (int p = tid; p < HALO * (WW / 4); p += NTHREADS) {
        const int j  = p / (WW / 4);
        const int vc = p - j * (WW / 4);
        const int h  = h0 + j - 1;
        float4 q0, q1, q2, q3;
        if ((unsigned)h < (unsigned)HH) {
            const float4* pr = (const float4*)(pred_bd + h * WW) + vc;
            const float4 x0 = pr[0];
            const float4 x1 = pr[CHSTR4];
            const float4 x2 = pr[2 * CHSTR4];
            const float4 x3 = pr[3 * CHSTR4];
            const int4   t  = ((const int4*)(tgt_bd + h * WW))[vc];
            {
                float e0 = __expf(x0.x), e1 = __expf(x1.x), e2 = __expf(x2.x), e3 = __expf(x3.x);
                float r = __frcp_rn(e0 + e1 + e2 + e3);
                q0.x = e0 * r - (t.x == 0); q1.x = e1 * r - (t.x == 1);
                q2.x = e2 * r - (t.x == 2); q3.x = e3 * r - (t.x == 3);
            }
            {
                float e0 = __expf(x0.y), e1 = __expf(x1.y), e2 = __expf(x2.y), e3 = __expf(x3.y);
                float r = __frcp_rn(e0 + e1 + e2 + e3);
                q0.y = e0 * r - (t.y == 0); q1.y = e1 * r - (t.y == 1);
                q2.y = e2 * r - (t.y == 2); q3.y = e3 * r - (t.y == 3);
            }
            {
                float e0 = __expf(x0.z), e1 = __expf(x1.z), e2 = __expf(x2.z), e3 = __expf(x3.z);
                float r = __frcp_rn(e0 + e1 + e2 + e3);
                q0.z = e0 * r - (t.z == 0); q1.z = e1 * r - (t.z == 1);
                q2.z = e2 * r - (t.z == 2); q3.z = e3 * r - (t.z == 3);
            }
            {
                float e0 = __expf(x0.w), e1 = __expf(x1.w), e2 = __expf(x2.w), e3 = __expf(x3.w);
                float r = __frcp_rn(e0 + e1 + e2 + e3);
                q0.w = e0 * r - (t.w == 0); q1.w = e1 * r - (t.w == 1);
                q2.w = e2 * r - (t.w == 2); q3.w = e3 * r - (t.w == 3);
            }
        } else {
            q0 = q1 = q2 = q3 = make_float4(0.f, 0.f, 0.f, 0.f);
        }
        const int sc = 4 + 4 * vc;
        *(float4*)&q[0][j][sc] = q0;
        *(float4*)&q[1][j][sc] = q1;
        *(float4*)&q[2][j][sc] = q2;
        *(float4*)&q[3][j][sc] = q3;
    }
    __syncthreads();

    // ---- Phase 2: separable sobel, packed f32x2, rolling 10-row window ----
    // thread -> (class c, 4-col group g, 8-row strip s)
    const int c   = tid / 80;
    const int rem = tid - c * 80;
    const int s   = rem / 40;
    const int g   = rem - s * 40;
    const int r0  = s * 8;
    const int cb  = 4 + 4 * g;

    const u64t TWO2 = pk2(2.f, 2.f);
    const float* rp = &q[c][r0][0];

    u64t pu01, pu23, pv01, pv23;   // row j-2 sums
    u64t cu01, cu23, cv01, cv23;   // row j-1 sums

#define ROW_UV(RP, U01, U23, V01, V23)                                  \
    {                                                                   \
        const float4 m = *(const float4*)((RP) + cb);                   \
        const float  lf = (RP)[cb - 1];                                 \
        const float  rf = (RP)[cb + 4];                                 \
        u64t A  = pk2(m.x, m.y);                                        \
        u64t Bv = pk2(m.z, m.w);                                        \
        u64t P0 = pk2(lf, m.x);                                         \
        u64t P2 = pk2(m.y, m.z);                                        \
        u64t P4 = pk2(m.w, rf);                                         \
        U01 = fma2v(A, TWO2, add2(P0, P2));                             \
        U23 = fma2v(Bv, TWO2, add2(P2, P4));                            \
        V01 = sub2(P2, P0);                                             \
        V23 = sub2(P4, P2);                                             \
    }

    ROW_UV(rp, pu01, pu23, pv01, pv23); rp += PITCH;
    ROW_UV(rp, cu01, cu23, cv01, cv23); rp += PITCH;

    u64t ax01 = 0ull, ax23 = 0ull, ay01 = 0ull, ay23 = 0ull;

#pragma unroll
    for (int k = 0; k < 8; k++) {
        u64t nu01, nu23, nv01, nv23;
        ROW_UV(rp, nu01, nu23, nv01, nv23); rp += PITCH;
        u64t gx01 = fma2v(cv01, TWO2, add2(pv01, nv01));
        u64t gx23 = fma2v(cv23, TWO2, add2(pv23, nv23));
        u64t gy01 = sub2(nu01, pu01);
        u64t gy23 = sub2(nu23, pu23);
        ax01 = fma2v(gx01, gx01, ax01);
        ax23 = fma2v(gx23, gx23, ax23);
        ay01 = fma2v(gy01, gy01, ay01);
        ay23 = fma2v(gy23, gy23, ay23);
        pu01 = cu01; pu23 = cu23; pv01 = cv01; pv23 = cv23;
        cu01 = nu01; cu23 = nu23; cv01 = nv01; cv23 = nv23;
    }
#undef ROW_UV

    float a0, a1, a2, a3, y0, y1, y2, y3;
    upk2(a0, a1, ax01); upk2(a2, a3, ax23);
    upk2(y0, y1, ay01); upk2(y2, y3, ay23);
    float acc = ((a0 + a1) + (a2 + a3)) + 2.f * ((y0 + y1) + (y2 + y3));

    // ---- block reduction -> per-block partial ----
#pragma unroll
    for (int o = 16; o > 0; o >>= 1)
        acc += __shfl_down_sync(0xffffffffu, acc, o);
    if ((tid & 31) == 0) warpsum[tid >> 5] = acc;
    __syncthreads();

    if (tid == 0) {
        float sm = 0.f;
#pragma unroll
        for (int i = 0; i < NTHREADS / 32; i++) sm += warpsum[i];
        g_partial[blk] = sm;
        __threadfence();
        is_last = (atomicAdd(&g_count, 1) == NBLK - 1);
    }
    __syncthreads();

    // ---- last block: final reduction + output + counter reset ----
    if (is_last) {
        double sd = 0.0;
        for (int i = tid; i < NBLK; i += NTHREADS) sd += (double)g_partial[i];
#pragma unroll
        for (int o = 16; o > 0; o >>= 1)
            sd += __shfl_down_sync(0xffffffffu, sd, o);
        if ((tid & 31) == 0) dwarpsum[tid >> 5] = sd;
        __syncthreads();
        if (tid == 0) {
            double tot = 0.0;
#pragma unroll
            for (int i = 0; i < NTHREADS / 32; i++) tot += dwarpsum[i];
            const double per_tensor = (double)BB * (DD + 2) * (HH + 2) * (WW + 2);
            out[0] = (float)(tot / per_tensor / (double)CC);
            g_count = 0;
        }
    }
}

extern "C" void kernel_launch(void* const* d_in, const int* in_sizes, int n_in,
                              void* d_out, int out_size)
{
    const float* pred   = (const float*)d_in[0];
    const int*   target = (const int*)d_in[1];
    float*       out    = (float*)d_out;

    bl_main_kernel<<<NBLK, NTHREADS>>>(pred, target, out);
}

// round 4
// speedup vs baseline: 1.5219x; 1.5219x over previous
#include <cuda_runtime.h>
#include <cuda_bf16.h>

// BoundaryLoss: loss = sum_{b,c,d,h,w} Gx(q)^2 + 2*Gy(q)^2 (normalized),
// q = softmax(pred, axis=C) - onehot(target); 2-D sobel per depth slice.
// pred (2,4,96,160,160) f32, target (2,96,160,160) i32.

#define BB 2
#define CC 4
#define DD 96
#define HH 160
#define WW 160

#define TH 16                       // output rows per block
#define HALO (TH + 2)               // 18
#define RTILES (HH / TH)            // 10
#define NBLK (BB * DD * RTILES)     // 1920
#define NTHREADS 320
#define PITCH 168                   // [4 guard][160 data][4 guard]

#define CHSTR (DD * HH * WW)
#define CHSTR4 (CHSTR / 4)

__device__ float g_partial[NBLK];
__device__ int   g_count = 0;

__global__ __launch_bounds__(NTHREADS, 4)
void bl_main_kernel(const float* __restrict__ pred,
                    const int*   __restrict__ target,
                    float*       __restrict__ out)
{
    __shared__ float q[CC][HALO][PITCH];       // 48384 B
    __shared__ float warpsum[NTHREADS / 32];
    __shared__ double dwarpsum[NTHREADS / 32];
    __shared__ bool  is_last;

    const int blk   = blockIdx.x;
    const int rt    = blk % RTILES;
    const int slice = blk / RTILES;
    const int b     = slice / DD;
    const int d     = slice - b * DD;
    const int h0    = rt * TH;

    const float* pred_bd = pred + (size_t)(b * CC * DD + d) * (HH * WW);
    const int*   tgt_bd  = target + (size_t)(b * DD + d) * (HH * WW);

    const int tid = threadIdx.x;

    // ---- guard columns: zero [0..3] and [164..167] for every (c,row) ----
    if (tid < CC * HALO * 2) {
        const int c    = tid / (HALO * 2);
        const int rem  = tid - c * (HALO * 2);
        const int row  = rem >> 1;
        const int side = rem & 1;
        *(float4*)&q[c][row][side ? (4 + WW) : 0] = make_float4(0.f, 0.f, 0.f, 0.f);
    }

    // ---- Phase 1: q = softmax - onehot (no max-sub; inputs are O(1)) ----
    for (int p = tid; p < HALO * (WW / 4); p += NTHREADS) {
        const int j  = p / (WW / 4);
        const int vc = p - j * (WW / 4);
        const int h  = h0 + j - 1;
        float4 q0, q1, q2, q3;
        if ((unsigned)h < (unsigned)HH) {
            const float4* pr = (const float4*)(pred_bd + h * WW) + vc;
            const float4 x0 = pr[0];
            const float4 x1 = pr[CHSTR4];
            const float4 x2 = pr[2 * CHSTR4];
            const float4 x3 = pr[3 * CHSTR4];
            const int4   t  = ((const int4*)(tgt_bd + h * WW))[vc];
            {
                float e0 = __expf(x0.x), e1 = __expf(x1.x), e2 = __expf(x2.x), e3 = __expf(x3.x);
                float r = __frcp_rn(e0 + e1 + e2 + e3);
                q0.x = e0 * r - (t.x == 0); q1.x = e1 * r - (t.x == 1);
                q2.x = e2 * r - (t.x == 2); q3.x = e3 * r - (t.x == 3);
            }
            {
                float e0 = __expf(x0.y), e1 = __expf(x1.y), e2 = __expf(x2.y), e3 = __expf(x3.y);
                float r = __frcp_rn(e0 + e1 + e2 + e3);
                q0.y = e0 * r - (t.y == 0); q1.y = e1 * r - (t.y == 1);
                q2.y = e2 * r - (t.y == 2); q3.y = e3 * r - (t.y == 3);
            }
            {
                float e0 = __expf(x0.z), e1 = __expf(x1.z), e2 = __expf(x2.z), e3 = __expf(x3.z);
                float r = __frcp_rn(e0 + e1 + e2 + e3);
                q0.z = e0 * r - (t.z == 0); q1.z = e1 * r - (t.z == 1);
                q2.z = e2 * r - (t.z == 2); q3.z = e3 * r - (t.z == 3);
            }
            {
                float e0 = __expf(x0.w), e1 = __expf(x1.w), e2 = __expf(x2.w), e3 = __expf(x3.w);
                float r = __frcp_rn(e0 + e1 + e2 + e3);
                q0.w = e0 * r - (t.w == 0); q1.w = e1 * r - (t.w == 1);
                q2.w = e2 * r - (t.w == 2); q3.w = e3 * r - (t.w == 3);
            }
        } else {
            q0 = q1 = q2 = q3 = make_float4(0.f, 0.f, 0.f, 0.f);
        }
        const int sc = 4 + 4 * vc;
        *(float4*)&q[0][j][sc] = q0;
        *(float4*)&q[1][j][sc] = q1;
        *(float4*)&q[2][j][sc] = q2;
        *(float4*)&q[3][j][sc] = q3;
    }
    __syncthreads();

    // ---- Phase 2: separable sobel, scalar math, float4 smem loads ----
    // thread -> (class c, 4-col group g, 8-row strip s); 4*40*2 = 320
    const int c   = tid / 80;
    const int rem = tid - c * 80;
    const int s   = rem / 40;
    const int g   = rem - s * 40;
    const int r0  = s * 8;
    const int cb  = 4 + 4 * g;

    const float* rp = &q[c][r0][0];

    // row sums: u_i = a + 2b + c (h-kernel), v_i = c - a (w-derivative)
    float pu[4], pv[4], cu[4], cv[4];

#define ROW_UV(RP, U, V)                                        \
    {                                                           \
        const float4 m  = *(const float4*)((RP) + cb);          \
        const float  lf = (RP)[cb - 1];                         \
        const float  rf = (RP)[cb + 4];                         \
        U[0] = (lf  + m.y) + 2.f * m.x;  V[0] = m.y - lf;       \
        U[1] = (m.x + m.z) + 2.f * m.y;  V[1] = m.z - m.x;      \
        U[2] = (m.y + m.w) + 2.f * m.z;  V[2] = m.w - m.y;      \
        U[3] = (m.z + rf ) + 2.f * m.w;  V[3] = rf  - m.z;      \
    }

    ROW_UV(rp, pu, pv); rp += PITCH;
    ROW_UV(rp, cu, cv); rp += PITCH;

    float ax = 0.f, ay = 0.f;
#pragma unroll
    for (int k = 0; k < 8; k++) {
        float nu[4], nv[4];
        ROW_UV(rp, nu, nv); rp += PITCH;
#pragma unroll
        for (int i = 0; i < 4; i++) {
            const float gx = (pv[i] + nv[i]) + 2.f * cv[i];
            const float gy = nu[i] - pu[i];
            ax += gx * gx;
            ay += gy * gy;
            pu[i] = cu[i]; pv[i] = cv[i];
            cu[i] = nu[i]; cv[i] = nv[i];
        }
    }
#undef ROW_UV

    float acc = ax + 2.f * ay;

    // ---- block reduction -> per-block partial ----
#pragma unroll
    for (int o = 16; o > 0; o >>= 1)
        acc += __shfl_down_sync(0xffffffffu, acc, o);
    if ((tid & 31) == 0) warpsum[tid >> 5] = acc;
    __syncthreads();

    if (tid == 0) {
        float sm = 0.f;
#pragma unroll
        for (int i = 0; i < NTHREADS / 32; i++) sm += warpsum[i];
        g_partial[blk] = sm;
        __threadfence();
        is_last = (atomicAdd(&g_count, 1) == NBLK - 1);
    }
    __syncthreads();

    // ---- last block: final reduction + output + counter reset ----
    if (is_last) {
        double sd = 0.0;
        for (int i = tid; i < NBLK; i += NTHREADS) sd += (double)g_partial[i];
#pragma unroll
        for (int o = 16; o > 0; o >>= 1)
            sd += __shfl_down_sync(0xffffffffu, sd, o);
        if ((tid & 31) == 0) dwarpsum[tid >> 5] = sd;
        __syncthreads();
        if (tid == 0) {
            double tot = 0.0;
#pragma unroll
            for (int i = 0; i < NTHREADS / 32; i++) tot += dwarpsum[i];
            const double per_tensor = (double)BB * (DD + 2) * (HH + 2) * (WW + 2);
            out[0] = (float)(tot / per_tensor / (double)CC);
            g_count = 0;
        }
    }
}

extern "C" void kernel_launch(void* const* d_in, const int* in_sizes, int n_in,
                              void* d_out, int out_size)
{
    const float* pred   = (const float*)d_in[0];
    const int*   target = (const int*)d_in[1];
    float*       out    = (float*)d_out;

    bl_main_kernel<<<NBLK, NTHREADS>>>(pred, target, out);
}